// round 4
// baseline (speedup 1.0000x reference)
#include <cuda_runtime.h>
#include <math.h>

#define NB    16
#define NPTS  1620
#define KNN_K 32
#define DD    64
#define CC    128
#define NSAMP (NB*NPTS*KNN_K)       // 829440, 6480 tiles of 128
#define EPSV  1e-5f

// ------------------------- scratch (static device globals) -------------------------
__device__ __align__(16) float g_featsT[NB*NPTS*DD];     // (b,n,d)
__device__ int   g_idx[NB*NPTS*KNN_K];
__device__ __align__(16) float g_y1[NSAMP*CC];           // channel-major: y1[c*NSAMP + s]
__device__ __align__(16) float g_y2[NSAMP*CC];           // channel-major
__device__ float g_stat[512];                            // [sum1|sq1|sum2|sq2] x 128
__device__ float g_scale[256];
__device__ float g_shift[256];

// ------------------------- f32x2 packed fp32 helpers (sm_103a) -------------------------
__device__ __forceinline__ void ffma2(unsigned long long& d, unsigned long long a, unsigned long long b) {
    asm("fma.rn.f32x2 %0, %1, %2, %0;" : "+l"(d) : "l"(a), "l"(b));
}
__device__ __forceinline__ unsigned long long dup2(float f) {
    unsigned long long r; asm("mov.b64 %0, {%1, %1};" : "=l"(r) : "f"(f)); return r;
}
__device__ __forceinline__ void unpack2(unsigned long long v, float& lo, float& hi) {
    asm("mov.b64 {%0, %1}, %2;" : "=f"(lo), "=f"(hi) : "l"(v));
}

// ------------------------- 0: zero stats -------------------------
__global__ void zero_stats_kernel() {
    const int t = threadIdx.x;
#pragma unroll
    for (int i = 0; i < 4; ++i) g_stat[t + 128*i] = 0.f;
}

// ------------------------- 1: transpose x (B,D,N) -> featsT (B,N,D) -------------------------
__global__ __launch_bounds__(256) void transpose_kernel(const float* __restrict__ x)
{
    __shared__ float tile[16][DD + 1];
    const int b = blockIdx.x, n0 = blockIdx.y * 16;
    const int t = threadIdx.x;
    const int nn = t & 15, dbq = t >> 4;
#pragma unroll
    for (int i = 0; i < 4; ++i) {
        const int d = i*16 + dbq;
        const int n = n0 + nn;
        tile[nn][d] = (n < NPTS) ? x[((size_t)b*DD + d)*NPTS + n] : 0.f;
    }
    __syncthreads();
    const int d2 = t & 63, nb2 = t >> 6;
#pragma unroll
    for (int i = 0; i < 4; ++i) {
        const int nn2 = nb2 + i*4;
        const int n = n0 + nn2;
        if (n < NPTS) g_featsT[((size_t)b*NPTS + n)*DD + d2] = tile[nn2][d2];
    }
}

// ------------------------- 2: KNN top-32 (smallest dist, tie -> lower index) -------------------------
__global__ __launch_bounds__(256) void knn_kernel(const float* __restrict__ coords)
{
    __shared__ float4 spts[NPTS];   // (x,y,z,|p|^2)  25.9 KB
    const int b = blockIdx.x, t = threadIdx.x;
    for (int i = t; i < NPTS; i += 256) {
        const float* cp = coords + (size_t)(b*NPTS + i)*3;
        const float px = cp[0], py = cp[1], pz = cp[2];
        spts[i] = make_float4(px, py, pz, px*px + py*py + pz*pz);
    }
    __syncthreads();
    const int q = blockIdx.y * 256 + t;
    if (q >= NPTS) return;
    const float4 me = spts[q];
    float bd[KNN_K]; int bi[KNN_K];
#pragma unroll
    for (int j = 0; j < KNN_K; ++j) { bd[j] = 3.4e38f; bi[j] = 0; }
    float worst = 3.4e38f;
    for (int m = 0; m < NPTS; ++m) {
        const float4 o = spts[m];
        const float d = me.w + o.w - 2.f*(me.x*o.x + me.y*o.y + me.z*o.z);
        if (d < worst) {                 // strict: equal-to-worst keeps earlier index (top_k stable)
            int p = KNN_K - 1;
            #pragma unroll 1
            while (p > 0 && bd[p-1] > d) { bd[p] = bd[p-1]; bi[p] = bi[p-1]; --p; }
            bd[p] = d; bi[p] = m;
            worst = bd[KNN_K-1];
        }
    }
    int* op = g_idx + (size_t)(b*NPTS + q)*KNN_K;
#pragma unroll
    for (int j = 0; j < KNN_K; ++j) op[j] = bi[j];
}

// ------------------------- 3/5: fused gather + 128x128x128 GEMM + stats -------------------------
// LAYER 0: As = nf gather (neighbor-center | center), W = w1, out = g_y1, statBase = 0
// LAYER 1: As = bnrelu1(y1), W = w2, out = g_y2, statBase = 256
// smem: As[128 k][128 s] (16384 f) + Bs[128 k][128 o] (16384 f) = 131072 bytes
template<int LAYER>
__global__ __launch_bounds__(256, 1) void gemm_kernel(const float* __restrict__ W)
{
    extern __shared__ float smem[];
    float* As = smem;
    float* Bs = smem + 16384;
    const int t = threadIdx.x;
    const int blk = blockIdx.x;
    const int s0 = blk * 128;
    const int lane = t & 31;

    // ---- Bs[c][o] = W[o][c]  (o fast across warp -> conflict-free smem writes)
    {
        const int o = t & 127;
        const int cq0 = t >> 7;  // 0..1
#pragma unroll
        for (int qq = 0; qq < 16; ++qq) {
            const int cq = cq0 + qq*2;   // 0..31
            const float4 v = *(const float4*)(W + o*CC + cq*4);
            Bs[(cq*4+0)*128 + o] = v.x;
            Bs[(cq*4+1)*128 + o] = v.y;
            Bs[(cq*4+2)*128 + o] = v.z;
            Bs[(cq*4+3)*128 + o] = v.w;
        }
    }

    // ---- As gather (k-major, plain layout)
    if (LAYER == 0) {
        // 405 tiles per batch (51840/128), tiles never straddle batches; 128 samples = 4 n's x 32 k's
        const int b  = blk / 405;
        const int r0 = (blk % 405) * 128;
        const int s  = t >> 1;
        const int half = t & 1;
        const int n  = r0/KNN_K + (s >> 5);
        const int kk = s & 31;
        const int nbr = g_idx[(b*NPTS + n)*KNN_K + kk];
        const float4* nrow = (const float4*)(g_featsT + (size_t)(b*NPTS + nbr)*DD);
        const float4* crow = (const float4*)(g_featsT + (size_t)(b*NPTS + n)*DD);
#pragma unroll
        for (int j = 0; j < 8; ++j) {
            const int d = half*32 + j*4;
            const float4 nv = nrow[d >> 2];
            const float4 cv = crow[d >> 2];
            As[(d+0)*128 + s] = nv.x - cv.x;
            As[(d+1)*128 + s] = nv.y - cv.y;
            As[(d+2)*128 + s] = nv.z - cv.z;
            As[(d+3)*128 + s] = nv.w - cv.w;
            As[(64+d+0)*128 + s] = cv.x;
            As[(64+d+1)*128 + s] = cv.y;
            As[(64+d+2)*128 + s] = cv.z;
            As[(64+d+3)*128 + s] = cv.w;
        }
    } else {
        // y1 is channel-major: coalesced 512B row reads, conflict-free vector smem writes
        const int kk0 = t >> 5;   // 0..7
#pragma unroll 1
        for (int pass = 0; pass < 16; ++pass) {
            const int kk = kk0 + pass*8;
            const float scl = g_scale[kk];
            const float shf = g_shift[kk];
            const float4 v = *(const float4*)(g_y1 + (size_t)kk*NSAMP + s0 + lane*4);
            float4 r;
            r.x = fmaxf(fmaf(v.x, scl, shf), 0.f);
            r.y = fmaxf(fmaf(v.y, scl, shf), 0.f);
            r.z = fmaxf(fmaf(v.z, scl, shf), 0.f);
            r.w = fmaxf(fmaf(v.w, scl, shf), 0.f);
            *(float4*)(As + kk*128 + lane*4) = r;
        }
    }
    __syncthreads();

    // ---- compute: thread = 8 rows (4 adjacent pairs) x 8 cols (stride 16)
    const int tx = t & 15;
    const int ty = t >> 4;
    const int rbase = ty * 8;
    unsigned long long acc[4][8];
#pragma unroll
    for (int p = 0; p < 4; ++p)
#pragma unroll
        for (int j = 0; j < 8; ++j) acc[p][j] = 0ull;

#pragma unroll 4
    for (int kk = 0; kk < 128; ++kk) {
        const float* ap = As + kk*128 + rbase;
        const unsigned long long a0 = *(const unsigned long long*)(ap + 0);
        const unsigned long long a1 = *(const unsigned long long*)(ap + 2);
        const unsigned long long a2 = *(const unsigned long long*)(ap + 4);
        const unsigned long long a3 = *(const unsigned long long*)(ap + 6);
        const float* bp = Bs + kk*128 + tx;
        unsigned long long bb[8];
#pragma unroll
        for (int j = 0; j < 8; ++j) bb[j] = dup2(bp[16*j]);
#pragma unroll
        for (int j = 0; j < 8; ++j) {
            ffma2(acc[0][j], a0, bb[j]);
            ffma2(acc[1][j], a1, bb[j]);
            ffma2(acc[2][j], a2, bb[j]);
            ffma2(acc[3][j], a3, bb[j]);
        }
    }
    __syncthreads();

    // ---- stage channel-major into As with XOR swizzle (kills 16-way write conflicts)
#pragma unroll
    for (int p = 0; p < 4; ++p) {
        const int r = rbase + 2*p;
#pragma unroll
        for (int j = 0; j < 8; ++j) {
            const int c = tx + 16*j;
            const int sw = 4*(c & 7);
            float lo, hi;
            unpack2(acc[p][j], lo, hi);
            As[c*128 + (r ^ sw)]       = lo;
            As[c*128 + ((r+1) ^ sw)]   = hi;
        }
    }
    __syncthreads();

    // ---- coalesced channel-major store + per-channel sum/sumsq
    float* outT = (LAYER == 0) ? g_y1 : g_y2;
    const int statBase = (LAYER == 0) ? 0 : 256;
    const int c0 = t >> 5;   // warp owns one channel per pass
#pragma unroll 1
    for (int pass = 0; pass < 16; ++pass) {
        const int c = c0 + pass*8;
        const int sw = 4*(c & 7);
        const float4 v = *(const float4*)(As + c*128 + ((lane*4) ^ sw));
        *(float4*)(outT + (size_t)c*NSAMP + s0 + lane*4) = v;
        float ls = v.x + v.y + v.z + v.w;
        float lq = v.x*v.x + v.y*v.y + v.z*v.z + v.w*v.w;
#pragma unroll
        for (int off = 16; off > 0; off >>= 1) {
            ls += __shfl_down_sync(0xffffffffu, ls, off);
            lq += __shfl_down_sync(0xffffffffu, lq, off);
        }
        if (lane == 0) {
            atomicAdd(&g_stat[statBase + c], ls);
            atomicAdd(&g_stat[statBase + 128 + c], lq);
        }
    }
}

// ------------------------- 4/6: BN stats finalize -------------------------
__global__ void finalize_kernel(const float* __restrict__ g, const float* __restrict__ bp, int layer)
{
    const int c = threadIdx.x;
    const float inv = 1.0f / (float)NSAMP;
    const float mean = g_stat[layer*256 + c] * inv;
    const float var  = g_stat[layer*256 + 128 + c] * inv - mean*mean;
    const float rs = rsqrtf(var + EPSV);
    const float sc = g[c] * rs;
    g_scale[layer*128 + c] = sc;
    g_shift[layer*128 + c] = bp[c] - mean * sc;
}

// ------------------------- 7: max over k + bn2 + relu -> out (B,C,N) -------------------------
__global__ __launch_bounds__(256) void maxpool_kernel(float* __restrict__ out)
{
    const int b = blockIdx.x;
    const int c = blockIdx.y;
    const float sc = g_scale[128 + c];
    const float sh = g_shift[128 + c];
    const float* base = g_y2 + (size_t)c*NSAMP + (size_t)b*NPTS*KNN_K;
    for (int n = threadIdx.x; n < NPTS; n += 256) {
        const float4* p = (const float4*)(base + n*KNN_K);
        float m = -3.4e38f;
#pragma unroll
        for (int q = 0; q < 8; ++q) {
            const float4 v = p[q];
            m = fmaxf(m, fmaxf(fmaxf(v.x, v.y), fmaxf(v.z, v.w)));
        }
        // scale > 0 (g=1): max commutes with bn; relu after max == max of relu
        out[((size_t)b*CC + c)*NPTS + n] = fmaxf(fmaf(m, sc, sh), 0.f);
    }
}

// ------------------------- launch -------------------------
extern "C" void kernel_launch(void* const* d_in, const int* in_sizes, int n_in,
                              void* d_out, int out_size)
{
    const float* x      = (const float*)d_in[0];
    const float* coords = (const float*)d_in[1];
    const float* w1     = (const float*)d_in[2];
    const float* g1     = (const float*)d_in[3];
    const float* b1     = (const float*)d_in[4];
    const float* w2     = (const float*)d_in[5];
    const float* g2     = (const float*)d_in[6];
    const float* b2     = (const float*)d_in[7];
    float* out = (float*)d_out;

    cudaFuncSetAttribute(gemm_kernel<0>, cudaFuncAttributeMaxDynamicSharedMemorySize, 131072);
    cudaFuncSetAttribute(gemm_kernel<1>, cudaFuncAttributeMaxDynamicSharedMemorySize, 131072);

    zero_stats_kernel<<<1, 128>>>();
    transpose_kernel<<<dim3(NB, (NPTS + 15)/16), 256>>>(x);
    knn_kernel<<<dim3(NB, (NPTS + 255)/256), 256>>>(coords);
    gemm_kernel<0><<<NSAMP/128, 256, 131072>>>(w1);
    finalize_kernel<<<1, 128>>>(g1, b1, 0);
    gemm_kernel<1><<<NSAMP/128, 256, 131072>>>(w2);
    finalize_kernel<<<1, 128>>>(g2, b2, 1);
    maxpool_kernel<<<dim3(NB, CC), 256>>>(out);
}

// round 5
// speedup vs baseline: 8.3386x; 8.3386x over previous
#include <cuda_runtime.h>
#include <math.h>

#define NB    16
#define NPTS  1620
#define KNN_K 32
#define DD    64
#define CC    128
#define NSAMP (NB*NPTS*KNN_K)       // 829440, 6480 tiles of 128
#define EPSV  1e-5f

// ------------------------- scratch (static device globals) -------------------------
__device__ __align__(16) float g_featsT[NB*NPTS*DD];     // (b,n,d)
__device__ int   g_idx[NB*NPTS*KNN_K];
__device__ __align__(16) float g_y1[NSAMP*CC];           // channel-major: y1[c*NSAMP + s]
__device__ __align__(16) float g_y2[NSAMP*CC];           // channel-major
__device__ float g_stat[512];                            // [sum1|sq1|sum2|sq2] x 128
__device__ float g_scale[256];
__device__ float g_shift[256];

// ------------------------- f32x2 packed fp32 helpers (sm_103a) -------------------------
__device__ __forceinline__ void ffma2(unsigned long long& d, unsigned long long a, unsigned long long b) {
    asm("fma.rn.f32x2 %0, %1, %2, %0;" : "+l"(d) : "l"(a), "l"(b));
}
__device__ __forceinline__ unsigned long long dup2(float f) {
    unsigned long long r; asm("mov.b64 %0, {%1, %1};" : "=l"(r) : "f"(f)); return r;
}
__device__ __forceinline__ void unpack2(unsigned long long v, float& lo, float& hi) {
    asm("mov.b64 {%0, %1}, %2;" : "=f"(lo), "=f"(hi) : "l"(v));
}

// ------------------------- 0: zero stats -------------------------
__global__ void zero_stats_kernel() {
    const int t = threadIdx.x;
#pragma unroll
    for (int i = 0; i < 4; ++i) g_stat[t + 128*i] = 0.f;
}

// ------------------------- 1: transpose x (B,D,N) -> featsT (B,N,D) -------------------------
__global__ __launch_bounds__(256) void transpose_kernel(const float* __restrict__ x)
{
    __shared__ float tile[16][DD + 1];
    const int b = blockIdx.x, n0 = blockIdx.y * 16;
    const int t = threadIdx.x;
    const int nn = t & 15, dbq = t >> 4;
#pragma unroll
    for (int i = 0; i < 4; ++i) {
        const int d = i*16 + dbq;
        const int n = n0 + nn;
        tile[nn][d] = (n < NPTS) ? x[((size_t)b*DD + d)*NPTS + n] : 0.f;
    }
    __syncthreads();
    const int d2 = t & 63, nb2 = t >> 6;
#pragma unroll
    for (int i = 0; i < 4; ++i) {
        const int nn2 = nb2 + i*4;
        const int n = n0 + nn2;
        if (n < NPTS) g_featsT[((size_t)b*NPTS + n)*DD + d2] = tile[nn2][d2];
    }
}

// ------------------------- 2: KNN, warp-cooperative bitonic top-32 -------------------------
// One warp per query. Lane l holds the l-th smallest (dist, idx) seen so far.
// Batch of 32 candidates per step; skip merge unless some candidate beats the worst kept.
__device__ __forceinline__ void cmpswap_lex(float& d, int& i, int j, bool up) {
    const unsigned FULL = 0xffffffffu;
    const float od = __shfl_xor_sync(FULL, d, j);
    const int   oi = __shfl_xor_sync(FULL, i, j);
    const bool lower = ((threadIdx.x & j) == 0);
    const bool selfS = (d < od) || (d == od && i < oi);
    if (selfS != (lower == up)) { d = od; i = oi; }
}

__global__ __launch_bounds__(256) void knn_kernel(const float* __restrict__ coords)
{
    __shared__ float4 spts[NPTS];   // (x,y,z,|p|^2)  25.9 KB
    const unsigned FULL = 0xffffffffu;
    const int b = blockIdx.x, t = threadIdx.x;
    for (int i = t; i < NPTS; i += 256) {
        const float* cp = coords + (size_t)(b*NPTS + i)*3;
        const float px = cp[0], py = cp[1], pz = cp[2];
        spts[i] = make_float4(px, py, pz, px*px + py*py + pz*pz);
    }
    __syncthreads();

    const int warp = t >> 5, lane = t & 31;
    const int q = blockIdx.y * 8 + warp;
    if (q >= NPTS) return;
    const float4 me = spts[q];

    float kd = 3.4e38f;
    int   ki = (1 << 30) + lane;

    for (int m0 = 0; m0 < NPTS; m0 += 32) {
        const int m = m0 + lane;
        float d; int mi;
        if (m < NPTS) {
            const float4 o = spts[m];
            d = me.w + o.w - 2.f*(me.x*o.x + me.y*o.y + me.z*o.z);
            mi = m;
        } else { d = 3.4e38f; mi = (1 << 30) + lane; }

        const float thr  = __shfl_sync(FULL, kd, 31);
        const int   thrI = __shfl_sync(FULL, ki, 31);
        const bool better = (d < thr) || (d == thr && mi < thrI);
        if (__any_sync(FULL, better)) {
            // bitonic sort the batch ascending (lex on (d, idx))
#pragma unroll
            for (int k = 2; k <= 32; k <<= 1) {
                const bool up = ((lane & k) == 0);
#pragma unroll
                for (int j = k >> 1; j >= 1; j >>= 1) cmpswap_lex(d, mi, j, up);
            }
            // reverse -> descending
            d  = __shfl_xor_sync(FULL, d, 31);
            mi = __shfl_xor_sync(FULL, mi, 31);
            // elementwise lex-min(kept asc, batch desc) -> bitonic sequence of the 32 smallest
            const bool keepS = (kd < d) || (kd == d && ki < mi);
            float nd = keepS ? kd : d;
            int   ni = keepS ? ki : mi;
            // bitonic merge ascending
#pragma unroll
            for (int j = 16; j >= 1; j >>= 1) cmpswap_lex(nd, ni, j, true);
            kd = nd; ki = ni;
        }
    }
    g_idx[((size_t)b*NPTS + q)*KNN_K + lane] = ki;
}

// ------------------------- 3/5: fused gather + 128x128x128 GEMM + stats -------------------------
// K split into 2 chunks of 64 -> smem 64KB, 2 CTAs/SM.
// smem: As[64 k][128 s] (8192 f) + Bs[64 k][128 o] (8192 f) = 65536 bytes
template<int LAYER>
__global__ __launch_bounds__(256, 2) void gemm_kernel(const float* __restrict__ W)
{
    extern __shared__ float smem[];
    float* As = smem;          // 8192 floats
    float* Bs = smem + 8192;   // 8192 floats
    const int t = threadIdx.x;
    const int blk = blockIdx.x;
    const int s0 = blk * 128;
    const int lane = t & 31;
    const int tx = t & 15;
    const int ty = t >> 4;
    const int rbase = ty * 8;

    unsigned long long acc[4][8];
#pragma unroll
    for (int p = 0; p < 4; ++p)
#pragma unroll
        for (int j = 0; j < 8; ++j) acc[p][j] = 0ull;

    // layer-0 gather indices (tiles never straddle batches: 405 tiles per batch)
    int bb = 0, nn = 0, kk_s = 0, s_half = 0;
    if (LAYER == 0) {
        bb = blk / 405;
        const int r0 = (blk % 405) * 128;
        const int s  = t >> 1;
        s_half = t & 1;
        nn = r0 / KNN_K + (s >> 5);
        kk_s = s & 31;
    }

#pragma unroll 1
    for (int kc = 0; kc < 2; ++kc) {
        __syncthreads();   // previous chunk compute done before overwriting smem

        // ---- Bs[c_local][o] = W[o][kc*64 + c_local]
        {
            const int o = t & 127;
            const int cb = (t >> 7) * 32;  // 0 or 32
#pragma unroll
            for (int qq = 0; qq < 8; ++qq) {
                const int cl = cb + qq*4;
                const float4 v = *(const float4*)(W + o*CC + kc*64 + cl);
                Bs[(cl+0)*128 + o] = v.x;
                Bs[(cl+1)*128 + o] = v.y;
                Bs[(cl+2)*128 + o] = v.z;
                Bs[(cl+3)*128 + o] = v.w;
            }
        }

        // ---- As gather
        if (LAYER == 0) {
            const int s = t >> 1;
            const int nbr = g_idx[((size_t)bb*NPTS + nn)*KNN_K + kk_s];
            const float4* crow = (const float4*)(g_featsT + (size_t)(bb*NPTS + nn)*DD);
            if (kc == 0) {
                const float4* nrow = (const float4*)(g_featsT + (size_t)(bb*NPTS + nbr)*DD);
#pragma unroll
                for (int j = 0; j < 8; ++j) {
                    const int d = s_half*32 + j*4;
                    const float4 nv = nrow[d >> 2];
                    const float4 cv = crow[d >> 2];
                    As[(d+0)*128 + s] = nv.x - cv.x;
                    As[(d+1)*128 + s] = nv.y - cv.y;
                    As[(d+2)*128 + s] = nv.z - cv.z;
                    As[(d+3)*128 + s] = nv.w - cv.w;
                }
            } else {
#pragma unroll
                for (int j = 0; j < 8; ++j) {
                    const int d = s_half*32 + j*4;
                    const float4 cv = crow[d >> 2];
                    As[(d+0)*128 + s] = cv.x;
                    As[(d+1)*128 + s] = cv.y;
                    As[(d+2)*128 + s] = cv.z;
                    As[(d+3)*128 + s] = cv.w;
                }
            }
        } else {
            // y1 channel-major: coalesced 512B rows, bn1 + relu applied inline
            const int kk0 = t >> 5;   // 0..7
#pragma unroll 1
            for (int pass = 0; pass < 8; ++pass) {
                const int kl = kk0 + pass*8;          // local row 0..63
                const int kg = kc*64 + kl;            // global channel
                const float scl = g_scale[kg];
                const float shf = g_shift[kg];
                const float4 v = *(const float4*)(g_y1 + (size_t)kg*NSAMP + s0 + lane*4);
                float4 r;
                r.x = fmaxf(fmaf(v.x, scl, shf), 0.f);
                r.y = fmaxf(fmaf(v.y, scl, shf), 0.f);
                r.z = fmaxf(fmaf(v.z, scl, shf), 0.f);
                r.w = fmaxf(fmaf(v.w, scl, shf), 0.f);
                *(float4*)(As + kl*128 + lane*4) = r;
            }
        }
        __syncthreads();

        // ---- compute chunk: thread = 8 rows (4 adjacent pairs) x 8 cols (stride 16)
#pragma unroll 4
        for (int kk = 0; kk < 64; ++kk) {
            const float* ap = As + kk*128 + rbase;
            const unsigned long long a0 = *(const unsigned long long*)(ap + 0);
            const unsigned long long a1 = *(const unsigned long long*)(ap + 2);
            const unsigned long long a2 = *(const unsigned long long*)(ap + 4);
            const unsigned long long a3 = *(const unsigned long long*)(ap + 6);
            const float* bp = Bs + kk*128 + tx;
            unsigned long long bv[8];
#pragma unroll
            for (int j = 0; j < 8; ++j) bv[j] = dup2(bp[16*j]);
#pragma unroll
            for (int j = 0; j < 8; ++j) {
                ffma2(acc[0][j], a0, bv[j]);
                ffma2(acc[1][j], a1, bv[j]);
                ffma2(acc[2][j], a2, bv[j]);
                ffma2(acc[3][j], a3, bv[j]);
            }
        }
    }

    // ---- epilogue: channel-major store + per-channel sum/sumsq, in 2 halves of 64 channels
    float* outT = (LAYER == 0) ? g_y1 : g_y2;
    const int statBase = (LAYER == 0) ? 0 : 256;
#pragma unroll 1
    for (int h = 0; h < 2; ++h) {
        __syncthreads();
        // stage: As[cl*128 + (r^sw)] with XOR swizzle; r even -> write float2
#pragma unroll
        for (int j4 = 0; j4 < 4; ++j4) {
            const int j = h*4 + j4;
            const int c = tx + 16*j;
            const int cl = c - h*64;
            const int sw = 4*(c & 7);
#pragma unroll
            for (int p = 0; p < 4; ++p) {
                const int r = rbase + 2*p;
                float lo, hi;
                unpack2(acc[p][j], lo, hi);
                *(float2*)(As + cl*128 + (r ^ sw)) = make_float2(lo, hi);
            }
        }
        __syncthreads();
        const int c0 = t >> 5;   // warp owns one channel per pass
#pragma unroll 1
        for (int pass = 0; pass < 8; ++pass) {
            const int cl = c0 + pass*8;
            const int c  = h*64 + cl;
            const int sw = 4*(c & 7);
            const float4 v = *(const float4*)(As + cl*128 + ((lane*4) ^ sw));
            *(float4*)(outT + (size_t)c*NSAMP + s0 + lane*4) = v;
            float ls = v.x + v.y + v.z + v.w;
            float lq = v.x*v.x + v.y*v.y + v.z*v.z + v.w*v.w;
#pragma unroll
            for (int off = 16; off > 0; off >>= 1) {
                ls += __shfl_down_sync(0xffffffffu, ls, off);
                lq += __shfl_down_sync(0xffffffffu, lq, off);
            }
            if (lane == 0) {
                atomicAdd(&g_stat[statBase + c], ls);
                atomicAdd(&g_stat[statBase + 128 + c], lq);
            }
        }
    }
}

// ------------------------- 4/6: BN stats finalize -------------------------
__global__ void finalize_kernel(const float* __restrict__ g, const float* __restrict__ bp, int layer)
{
    const int c = threadIdx.x;
    const float inv = 1.0f / (float)NSAMP;
    const float mean = g_stat[layer*256 + c] * inv;
    const float var  = g_stat[layer*256 + 128 + c] * inv - mean*mean;
    const float rs = rsqrtf(var + EPSV);
    const float sc = g[c] * rs;
    g_scale[layer*128 + c] = sc;
    g_shift[layer*128 + c] = bp[c] - mean * sc;
}

// ------------------------- 7: max over k + bn2 + relu -> out (B,C,N) -------------------------
__global__ __launch_bounds__(256) void maxpool_kernel(float* __restrict__ out)
{
    const int b = blockIdx.x;
    const int c = blockIdx.y;
    const float sc = g_scale[128 + c];
    const float sh = g_shift[128 + c];
    const float* base = g_y2 + (size_t)c*NSAMP + (size_t)b*NPTS*KNN_K;
    for (int n = threadIdx.x; n < NPTS; n += 256) {
        const float4* p = (const float4*)(base + n*KNN_K);
        float m = -3.4e38f;
#pragma unroll
        for (int q = 0; q < 8; ++q) {
            const float4 v = p[q];
            m = fmaxf(m, fmaxf(fmaxf(v.x, v.y), fmaxf(v.z, v.w)));
        }
        // scale > 0 (g=1): max commutes with bn; relu(max) == max(relu)
        out[((size_t)b*CC + c)*NPTS + n] = fmaxf(fmaf(m, sc, sh), 0.f);
    }
}

// ------------------------- launch -------------------------
extern "C" void kernel_launch(void* const* d_in, const int* in_sizes, int n_in,
                              void* d_out, int out_size)
{
    const float* x      = (const float*)d_in[0];
    const float* coords = (const float*)d_in[1];
    const float* w1     = (const float*)d_in[2];
    const float* g1     = (const float*)d_in[3];
    const float* b1     = (const float*)d_in[4];
    const float* w2     = (const float*)d_in[5];
    const float* g2     = (const float*)d_in[6];
    const float* b2     = (const float*)d_in[7];
    float* out = (float*)d_out;

    cudaFuncSetAttribute(gemm_kernel<0>, cudaFuncAttributeMaxDynamicSharedMemorySize, 65536);
    cudaFuncSetAttribute(gemm_kernel<1>, cudaFuncAttributeMaxDynamicSharedMemorySize, 65536);

    zero_stats_kernel<<<1, 128>>>();
    transpose_kernel<<<dim3(NB, (NPTS + 15)/16), 256>>>(x);
    knn_kernel<<<dim3(NB, (NPTS + 7)/8), 256>>>(coords);
    gemm_kernel<0><<<NSAMP/128, 256, 65536>>>(w1);
    finalize_kernel<<<1, 128>>>(g1, b1, 0);
    gemm_kernel<1><<<NSAMP/128, 256, 65536>>>(w2);
    finalize_kernel<<<1, 128>>>(g2, b2, 1);
    maxpool_kernel<<<dim3(NB, CC), 256>>>(out);
}

// round 9
// speedup vs baseline: 11.3462x; 1.3607x over previous
#include <cuda_runtime.h>
#include <cuda_bf16.h>
#include <cstdint>
#include <math.h>

#define NB    16
#define NPTS  1620
#define KNN_K 32
#define DD    64
#define CC    128
#define NSAMP (NB*NPTS*KNN_K)       // 829440 = 6480 tiles of 128
#define NTILE (NSAMP/128)           // 6480
#define TPB   405                   // tiles per batch
#define EPSV  1e-5f

#define RSB    272                  // bf16 tile row stride in bytes (136 elems: 128 + 8 pad)
#define TILE_B (128*RSB)            // 34816 bytes per bf16 tile
#define SMEM_DYN (4*TILE_B)         // Ahi, Alo, Bhi, Blo = 139264 B

// ------------------------- scratch (static device globals) -------------------------
__device__ __align__(16) float g_featsT[NB*NPTS*DD];       // (b,n,d)
__device__ int   g_idx[NB*NPTS*KNN_K];
__device__ __align__(16) float g_y1[(size_t)NSAMP*CC];     // channel-major y1[c*NSAMP + s]
__device__ __align__(16) float g_pool[(size_t)NB*NPTS*CC]; // raw max over k, (b,n,c)
__device__ float g_stat[512];                              // [sum1|sq1|sum2|sq2] x 128
__device__ float g_scale[256];
__device__ float g_shift[256];

// ------------------------- helpers -------------------------
__device__ __forceinline__ uint32_t smem_u32(const void* p) {
    uint32_t a; asm("{ .reg .u64 t; cvta.to.shared.u64 t, %1; cvt.u32.u64 %0, t; }" : "=r"(a) : "l"(p));
    return a;
}
__device__ __forceinline__ void ldsm_x4(uint32_t* r, uint32_t addr) {
    asm volatile("ldmatrix.sync.aligned.m8n8.x4.shared.b16 {%0,%1,%2,%3}, [%4];"
        : "=r"(r[0]), "=r"(r[1]), "=r"(r[2]), "=r"(r[3]) : "r"(addr));
}
__device__ __forceinline__ void mma_bf16(float* c, const uint32_t* a, const uint32_t* b) {
    asm volatile("mma.sync.aligned.m16n8k16.row.col.f32.bf16.bf16.f32 "
        "{%0,%1,%2,%3}, {%4,%5,%6,%7}, {%8,%9}, {%0,%1,%2,%3};"
        : "+f"(c[0]), "+f"(c[1]), "+f"(c[2]), "+f"(c[3])
        : "r"(a[0]), "r"(a[1]), "r"(a[2]), "r"(a[3]), "r"(b[0]), "r"(b[1]));
}
__device__ __forceinline__ uint32_t pack2(__nv_bfloat16 a, __nv_bfloat16 b) {
    return ((uint32_t)__bfloat16_as_ushort(b) << 16) | (uint32_t)__bfloat16_as_ushort(a);
}
// split 4 fp32 into bf16 hi + bf16 residual-lo; store 8B each into row-major padded tiles
__device__ __forceinline__ void store_hl4(char* hiP, char* loP, int row, int col, float4 v) {
    const int off = row*RSB + col*2;
    const __nv_bfloat16 bx = __float2bfloat16(v.x), by = __float2bfloat16(v.y);
    const __nv_bfloat16 bz = __float2bfloat16(v.z), bw = __float2bfloat16(v.w);
    uint2 hh; hh.x = pack2(bx, by); hh.y = pack2(bz, bw);
    *(uint2*)(hiP + off) = hh;
    const __nv_bfloat16 lx = __float2bfloat16(v.x - __bfloat162float(bx));
    const __nv_bfloat16 ly = __float2bfloat16(v.y - __bfloat162float(by));
    const __nv_bfloat16 lz = __float2bfloat16(v.z - __bfloat162float(bz));
    const __nv_bfloat16 lw = __float2bfloat16(v.w - __bfloat162float(bw));
    uint2 ll; ll.x = pack2(lx, ly); ll.y = pack2(lz, lw);
    *(uint2*)(loP + off) = ll;
}

// ------------------------- 0: zero stats -------------------------
__global__ void zero_stats_kernel() {
    const int t = threadIdx.x;
#pragma unroll
    for (int i = 0; i < 4; ++i) g_stat[t + 128*i] = 0.f;
}

// ------------------------- 1: transpose x (B,D,N) -> featsT (B,N,D) -------------------------
__global__ __launch_bounds__(256) void transpose_kernel(const float* __restrict__ x)
{
    __shared__ float tile[16][DD + 1];
    const int b = blockIdx.x, n0 = blockIdx.y * 16;
    const int t = threadIdx.x;
    const int nn = t & 15, dbq = t >> 4;
#pragma unroll
    for (int i = 0; i < 4; ++i) {
        const int d = i*16 + dbq;
        const int n = n0 + nn;
        tile[nn][d] = (n < NPTS) ? x[((size_t)b*DD + d)*NPTS + n] : 0.f;
    }
    __syncthreads();
    const int d2 = t & 63, nb2 = t >> 6;
#pragma unroll
    for (int i = 0; i < 4; ++i) {
        const int nn2 = nb2 + i*4;
        const int n = n0 + nn2;
        if (n < NPTS) g_featsT[((size_t)b*NPTS + n)*DD + d2] = tile[nn2][d2];
    }
}

// ------------------------- 2: KNN warp-bitonic top-32 -------------------------
__device__ __forceinline__ void cmpswap_lex(float& d, int& i, int j, bool up) {
    const unsigned FULL = 0xffffffffu;
    const float od = __shfl_xor_sync(FULL, d, j);
    const int   oi = __shfl_xor_sync(FULL, i, j);
    const bool lower = ((threadIdx.x & j) == 0);
    const bool selfS = (d < od) || (d == od && i < oi);
    if (selfS != (lower == up)) { d = od; i = oi; }
}
__global__ __launch_bounds__(256) void knn_kernel(const float* __restrict__ coords)
{
    __shared__ float4 spts[NPTS];
    const unsigned FULL = 0xffffffffu;
    const int b = blockIdx.x, t = threadIdx.x;
    for (int i = t; i < NPTS; i += 256) {
        const float* cp = coords + (size_t)(b*NPTS + i)*3;
        const float px = cp[0], py = cp[1], pz = cp[2];
        spts[i] = make_float4(px, py, pz, px*px + py*py + pz*pz);
    }
    __syncthreads();
    const int warp = t >> 5, lane = t & 31;
    const int q = blockIdx.y * 8 + warp;
    if (q >= NPTS) return;
    const float4 me = spts[q];
    float kd = 3.4e38f;
    int   ki = (1 << 30) + lane;
    for (int m0 = 0; m0 < NPTS; m0 += 32) {
        const int m = m0 + lane;
        float d; int mi;
        if (m < NPTS) {
            const float4 o = spts[m];
            d = me.w + o.w - 2.f*(me.x*o.x + me.y*o.y + me.z*o.z);
            mi = m;
        } else { d = 3.4e38f; mi = (1 << 30) + lane; }
        const float thr  = __shfl_sync(FULL, kd, 31);
        const int   thrI = __shfl_sync(FULL, ki, 31);
        const bool better = (d < thr) || (d == thr && mi < thrI);
        if (__any_sync(FULL, better)) {
#pragma unroll
            for (int k = 2; k <= 32; k <<= 1) {
                const bool up = ((lane & k) == 0);
#pragma unroll
                for (int j = k >> 1; j >= 1; j >>= 1) cmpswap_lex(d, mi, j, up);
            }
            d  = __shfl_xor_sync(FULL, d, 31);
            mi = __shfl_xor_sync(FULL, mi, 31);
            const bool keepS = (kd < d) || (kd == d && ki < mi);
            float nd = keepS ? kd : d;
            int   ni = keepS ? ki : mi;
#pragma unroll
            for (int j = 16; j >= 1; j >>= 1) cmpswap_lex(nd, ni, j, true);
            kd = nd; ki = ni;
        }
    }
    g_idx[((size_t)b*NPTS + q)*KNN_K + lane] = ki;
}

// ------------------------- 3/5: bf16x3 mma.sync GEMM (128x128x128 per tile) -------------------------
// Warp (wid&3)=wr owns rows wr*32..+31 (2 m16 frags), (wid>>2)=wc owns cols wc*64..+63 (8 n8 frags).
template<int LAYER>
__global__ __launch_bounds__(256, 1) void gemm_mma(const float* __restrict__ W)
{
    extern __shared__ char sb[];
    char* sAhi = sb;
    char* sAlo = sb + TILE_B;
    char* sBhi = sb + 2*TILE_B;
    char* sBlo = sb + 3*TILE_B;
    const int t = threadIdx.x, wid = t >> 5, lane = t & 31;
    const int blk = blockIdx.x, s0 = blk * 128;
    const int b = blk / TPB, r0 = (blk % TPB) * 128;
    const unsigned FULL = 0xffffffffu;

    // ---- B fill: row o (out channel), col c (in channel)
    {
        const int o = t >> 1, half = t & 1;
        const float4* wrow = (const float4*)(W + (size_t)o*CC + half*64);
#pragma unroll
        for (int j = 0; j < 16; ++j)
            store_hl4(sBhi, sBlo, o, half*64 + j*4, wrow[j]);
    }

    // ---- A fill: row s (sample), col c
    if (LAYER == 0) {
        const int s = t >> 1, half = t & 1;
        const int n  = r0 / KNN_K + (s >> 5);
        const int kk = s & 31;
        const int nbr = g_idx[((size_t)b*NPTS + n)*KNN_K + kk];
        const float4* crow = (const float4*)(g_featsT + (size_t)(b*NPTS + n)*DD);
        if (half == 0) {
            const float4* nrow = (const float4*)(g_featsT + (size_t)(b*NPTS + nbr)*DD);
#pragma unroll
            for (int j = 0; j < 16; ++j) {
                const float4 nv = nrow[j], cv = crow[j];
                float4 d; d.x = nv.x-cv.x; d.y = nv.y-cv.y; d.z = nv.z-cv.z; d.w = nv.w-cv.w;
                store_hl4(sAhi, sAlo, s, j*4, d);
            }
        } else {
#pragma unroll
            for (int j = 0; j < 16; ++j)
                store_hl4(sAhi, sAlo, s, 64 + j*4, crow[j]);
        }
    } else {
        // y1 channel-major: coalesced reads, bn1 + relu inline
#pragma unroll 1
        for (int i = 0; i < 4; ++i) {
            const int c = (wid + i*8) * 4;
            float sc0 = g_scale[c],   sh0 = g_shift[c];
            float sc1 = g_scale[c+1], sh1 = g_shift[c+1];
            float sc2 = g_scale[c+2], sh2 = g_shift[c+2];
            float sc3 = g_scale[c+3], sh3 = g_shift[c+3];
            const float* p0 = g_y1 + (size_t)(c+0)*NSAMP + s0;
            const float* p1 = g_y1 + (size_t)(c+1)*NSAMP + s0;
            const float* p2 = g_y1 + (size_t)(c+2)*NSAMP + s0;
            const float* p3 = g_y1 + (size_t)(c+3)*NSAMP + s0;
#pragma unroll
            for (int p = 0; p < 4; ++p) {
                const int row = p*32 + lane;
                float4 v;
                v.x = fmaxf(fmaf(p0[row], sc0, sh0), 0.f);
                v.y = fmaxf(fmaf(p1[row], sc1, sh1), 0.f);
                v.z = fmaxf(fmaf(p2[row], sc2, sh2), 0.f);
                v.w = fmaxf(fmaf(p3[row], sc3, sh3), 0.f);
                store_hl4(sAhi, sAlo, row, c, v);
            }
        }
    }
    __syncthreads();

    // ---- mma mainloop: 3 passes (AhiBhi + AloBhi + AhiBlo)
    const uint32_t base = smem_u32(sb);
    const int wr = wid & 3, wc = wid >> 2;
    const uint32_t arow = (uint32_t)((wr*32 + (lane & 15))*RSB + ((lane >> 4) * 8) * 2);
    const uint32_t brow = (uint32_t)((wc*64 + (lane & 7) + ((lane >> 4) << 3))*RSB + (((lane >> 3) & 1) * 8) * 2);

    float acc[2][8][4];
#pragma unroll
    for (int mi = 0; mi < 2; ++mi)
#pragma unroll
        for (int nf = 0; nf < 8; ++nf)
#pragma unroll
            for (int e = 0; e < 4; ++e) acc[mi][nf][e] = 0.f;

    const uint32_t aOff[3] = {0u, (uint32_t)TILE_B, 0u};
    const uint32_t bOff[3] = {2u*TILE_B, 2u*TILE_B, 3u*TILE_B};
#pragma unroll 1
    for (int pass = 0; pass < 3; ++pass) {
        const uint32_t aP = base + aOff[pass] + arow;
        const uint32_t bP = base + bOff[pass] + brow;
#pragma unroll
        for (int ks = 0; ks < 8; ++ks) {
            const uint32_t ko = (uint32_t)(ks * 32);   // 16 bf16 = 32B per k-step
            uint32_t a0[4], a1[4];
            ldsm_x4(a0, aP + ko);
            ldsm_x4(a1, aP + 16*RSB + ko);
            uint32_t bf[8][2];
#pragma unroll
            for (int bi = 0; bi < 4; ++bi) {
                uint32_t r[4];
                ldsm_x4(r, bP + (uint32_t)(bi*16*RSB) + ko);
                bf[bi*2][0] = r[0]; bf[bi*2][1] = r[1];
                bf[bi*2+1][0] = r[2]; bf[bi*2+1][1] = r[3];
            }
#pragma unroll
            for (int nf = 0; nf < 8; ++nf) {
                mma_bf16(acc[0][nf], a0, bf[nf]);
                mma_bf16(acc[1][nf], a1, bf[nf]);
            }
        }
    }

    // ---- epilogue
    if (LAYER == 0) {
        __syncthreads();
        float* S = (float*)sb;          // [128 c][132 row] fp32, reuses A tiles (67.5KB)
        const int q2 = (lane & 3) * 2, rr = lane >> 2;
#pragma unroll
        for (int mi = 0; mi < 2; ++mi)
#pragma unroll
            for (int nf = 0; nf < 8; ++nf) {
                const int c = wc*64 + nf*8 + q2;
                const int r = wr*32 + mi*16 + rr;
                S[c*132 + r]         = acc[mi][nf][0];
                S[(c+1)*132 + r]     = acc[mi][nf][1];
                S[c*132 + r + 8]     = acc[mi][nf][2];
                S[(c+1)*132 + r + 8] = acc[mi][nf][3];
            }
        __syncthreads();
#pragma unroll 1
        for (int i = 0; i < 16; ++i) {
            const int c = wid + i*8;
            const float4 v = *(const float4*)(S + c*132 + lane*4);
            *(float4*)(g_y1 + (size_t)c*NSAMP + s0 + lane*4) = v;
            float sv = v.x + v.y + v.z + v.w;
            float qv = v.x*v.x + v.y*v.y + v.z*v.z + v.w*v.w;
#pragma unroll
            for (int o = 16; o > 0; o >>= 1) {
                sv += __shfl_xor_sync(FULL, sv, o);
                qv += __shfl_xor_sync(FULL, qv, o);
            }
            if (lane == 0) { atomicAdd(&g_stat[c], sv); atomicAdd(&g_stat[128 + c], qv); }
        }
    } else {
        // warp wr's 32 rows = all k of n_local = wr -> in-register max over k + bn2 stats
        __syncthreads();
        float* ps = (float*)sb;         // [4 n][128 c]
#pragma unroll
        for (int nf = 0; nf < 8; ++nf) {
#pragma unroll
            for (int e = 0; e < 2; ++e) {
                const float v0 = acc[0][nf][e],   v1 = acc[0][nf][e+2];
                const float v2 = acc[1][nf][e],   v3 = acc[1][nf][e+2];
                float mx = fmaxf(fmaxf(v0, v1), fmaxf(v2, v3));
                float sv = v0 + v1 + v2 + v3;
                float qv = v0*v0 + v1*v1 + v2*v2 + v3*v3;
#pragma unroll
                for (int o = 4; o <= 16; o <<= 1) {
                    mx  = fmaxf(mx, __shfl_xor_sync(FULL, mx, o));
                    sv += __shfl_xor_sync(FULL, sv, o);
                    qv += __shfl_xor_sync(FULL, qv, o);
                }
                if (lane < 4) {
                    const int c = wc*64 + nf*8 + lane*2 + e;
                    atomicAdd(&g_stat[256 + c], sv);
                    atomicAdd(&g_stat[384 + c], qv);
                    ps[wr*128 + c] = mx;
                }
            }
        }
        __syncthreads();
        if (t < 128) {
            const int nl = t >> 5, c4 = (t & 31) * 4;
            const int n0 = r0 / KNN_K;
            const float4 v = *(const float4*)(ps + nl*128 + c4);
            *(float4*)(g_pool + ((size_t)(b*NPTS + n0 + nl))*CC + c4) = v;
        }
    }
}

// ------------------------- 4/6: BN stats finalize -------------------------
__global__ void finalize_kernel(const float* __restrict__ g, const float* __restrict__ bp, int layer)
{
    const int c = threadIdx.x;
    const float inv = 1.0f / (float)NSAMP;
    const float mean = g_stat[layer*256 + c] * inv;
    const float var  = g_stat[layer*256 + 128 + c] * inv - mean*mean;
    const float rs = rsqrtf(var + EPSV);
    const float sc = g[c] * rs;
    g_scale[layer*128 + c] = sc;
    g_shift[layer*128 + c] = bp[c] - mean * sc;
}

// ------------------------- 7: bn2 + relu + transpose (b,n,c) -> (b,c,n) -------------------------
// scale > 0 (g=1): bn commutes with max; relu(max) == max(relu)
__global__ __launch_bounds__(256) void final_kernel(float* __restrict__ out)
{
    __shared__ float tile[32][33];
    const int b = blockIdx.x, n0 = blockIdx.y * 32, c0 = blockIdx.z * 32;
    const int t = threadIdx.x;
    const int cl = t & 31, rl = t >> 5;
#pragma unroll
    for (int i = 0; i < 4; ++i) {
        const int n = n0 + rl + i*8;
        tile[rl + i*8][cl] = (n < NPTS) ? g_pool[((size_t)b*NPTS + n)*CC + c0 + cl] : 0.f;
    }
    __syncthreads();
#pragma unroll
    for (int i = 0; i < 4; ++i) {
        const int c = c0 + rl + i*8;
        const int n = n0 + cl;
        if (n < NPTS) {
            const float v = tile[cl][rl + i*8];
            out[((size_t)b*CC + c)*NPTS + n] = fmaxf(fmaf(v, g_scale[128 + c], g_shift[128 + c]), 0.f);
        }
    }
}

// ------------------------- launch -------------------------
extern "C" void kernel_launch(void* const* d_in, const int* in_sizes, int n_in,
                              void* d_out, int out_size)
{
    const float* x      = (const float*)d_in[0];
    const float* coords = (const float*)d_in[1];
    const float* w1     = (const float*)d_in[2];
    const float* g1     = (const float*)d_in[3];
    const float* b1     = (const float*)d_in[4];
    const float* w2     = (const float*)d_in[5];
    const float* g2     = (const float*)d_in[6];
    const float* b2     = (const float*)d_in[7];
    float* out = (float*)d_out;

    cudaFuncSetAttribute(gemm_mma<0>, cudaFuncAttributeMaxDynamicSharedMemorySize, SMEM_DYN);
    cudaFuncSetAttribute(gemm_mma<1>, cudaFuncAttributeMaxDynamicSharedMemorySize, SMEM_DYN);

    zero_stats_kernel<<<1, 128>>>();
    transpose_kernel<<<dim3(NB, (NPTS + 15)/16), 256>>>(x);
    knn_kernel<<<dim3(NB, (NPTS + 7)/8), 256>>>(coords);
    gemm_mma<0><<<NTILE, 256, SMEM_DYN>>>(w1);
    finalize_kernel<<<1, 128>>>(g1, b1, 0);
    gemm_mma<1><<<NTILE, 256, SMEM_DYN>>>(w2);
    finalize_kernel<<<1, 128>>>(g2, b2, 1);
    final_kernel<<<dim3(NB, (NPTS + 31)/32, CC/32), 256>>>(out);
}